// round 6
// baseline (speedup 1.0000x reference)
#include <cuda_runtime.h>
#include <cstdint>

#define BH      16
#define LSEQ    4096
#define DIM     128
#define CHK     32
#define DV      16
#define NSLICE  8
#define NCHUNK  (LSEQ / CHK)
#define PD      132   // padded row length (floats), 528B, 16B-aligned
#define THR2    512

typedef unsigned long long ull;

// ---- scratch (device globals; allocation-free) ----
__device__ float g_QN[(size_t)BH * LSEQ * DIM];
__device__ float g_KN[(size_t)BH * LSEQ * DIM];
__device__ float g_W [(size_t)BH * LSEQ * DIM];
__device__ float g_U [(size_t)BH * LSEQ * DIM];
__device__ float g_AT[(size_t)BH * NCHUNK * CHK * CHK];

// ---- packed f32x2 helpers ----
__device__ __forceinline__ ull ffma2(ull a, ull b, ull c) {
    ull d;
    asm("fma.rn.f32x2 %0, %1, %2, %3;" : "=l"(d) : "l"(a), "l"(b), "l"(c));
    return d;
}
__device__ __forceinline__ ull fadd2(ull a, ull b) {
    ull d;
    asm("add.rn.f32x2 %0, %1, %2;" : "=l"(d) : "l"(a), "l"(b));
    return d;
}
__device__ __forceinline__ ull pack2(float v) {
    ull d;
    asm("mov.b64 %0, {%1, %1};" : "=l"(d) : "f"(v));
    return d;
}
__device__ __forceinline__ float hadd2(ull v) {
    float lo, hi;
    asm("mov.b64 {%0, %1}, %2;" : "=f"(lo), "=f"(hi) : "l"(v));
    return lo + hi;
}
__device__ __forceinline__ ull shfl_xor64(ull v, int m) {
    uint32_t lo = (uint32_t)v, hi = (uint32_t)(v >> 32);
    lo = __shfl_xor_sync(0xffffffffu, lo, m);
    hi = __shfl_xor_sync(0xffffffffu, hi, m);
    return ((ull)hi << 32) | lo;
}

// ---- cp.async helpers ----
__device__ __forceinline__ void cp16(void* smem_dst, const void* gmem_src) {
    uint32_t s = (uint32_t)__cvta_generic_to_shared(smem_dst);
    asm volatile("cp.async.cg.shared.global [%0], [%1], 16;\n" :: "r"(s), "l"(gmem_src));
}
__device__ __forceinline__ void cp_commit() {
    asm volatile("cp.async.commit_group;\n" ::: "memory");
}
__device__ __forceinline__ void cp_wait_all() {
    asm volatile("cp.async.wait_group 0;\n" ::: "memory");
}

// ============================================================
// Kernel 1: fully parallel per-(bh,chunk) preparation
// ============================================================
struct SM1 {
    float Qn[CHK][PD];
    float Kn[CHK][PD];
    float Kb[CHK][PD];
    float Vb[CHK][PD];
    float T [CHK][CHK + 1];
    float beta[CHK], rq[CHK], rk[CHK];
};

extern "C" __global__ void __launch_bounds__(256)
k1_prepare(const float* __restrict__ q, const float* __restrict__ k,
           const float* __restrict__ v, const float* __restrict__ beta)
{
    extern __shared__ __align__(16) char smraw1[];
    SM1& sm = *reinterpret_cast<SM1*>(smraw1);
    const int ch = blockIdx.x, bh = blockIdx.y;
    const int tid = threadIdx.x, lane = tid & 31, warp = tid >> 5;
    const size_t base = ((size_t)bh * LSEQ + (size_t)ch * CHK) * DIM;

    for (int idx = tid; idx < CHK * DIM; idx += 256) {
        int r = idx >> 7, c = idx & 127;
        sm.Qn[r][c] = q[base + idx];
        sm.Kn[r][c] = k[base + idx];
        sm.Vb[r][c] = v[base + idx];
    }
    if (tid < CHK) sm.beta[tid] = beta[(size_t)bh * LSEQ + ch * CHK + tid];
    __syncthreads();

    { // row L2 norms
        int row = warp * 4 + (lane >> 3), sub = lane & 7;
        float sq = 0.f, sk = 0.f;
        #pragma unroll
        for (int t = 0; t < 16; t++) {
            float a  = sm.Qn[row][sub + 8 * t]; sq += a * a;
            float b2 = sm.Kn[row][sub + 8 * t]; sk += b2 * b2;
        }
        #pragma unroll
        for (int off = 4; off >= 1; off >>= 1) {
            sq += __shfl_xor_sync(0xffffffffu, sq, off);
            sk += __shfl_xor_sync(0xffffffffu, sk, off);
        }
        if (sub == 0) { sm.rq[row] = rsqrtf(sq); sm.rk[row] = rsqrtf(sk); }
    }
    __syncthreads();

    for (int idx = tid; idx < CHK * DIM; idx += 256) {
        int r = idx >> 7, c = idx & 127;
        float bt = sm.beta[r];
        float qn = sm.Qn[r][c] * sm.rq[r];
        float kn = sm.Kn[r][c] * sm.rk[r];
        sm.Qn[r][c] = qn;
        sm.Kn[r][c] = kn;
        sm.Kb[r][c] = kn * bt;
        sm.Vb[r][c] *= bt;
        g_QN[base + idx] = qn;
        g_KN[base + idx] = kn;
    }
    __syncthreads();

    { // T (strict lower, kb.kn) and At (causal, qn.kn), 2x2 tiles, f32x2 math
        int a = tid >> 4, b = tid & 15;
        int i0 = 2 * a, j0 = 2 * b;
        ull t00 = 0, t01 = 0, t10 = 0, t11 = 0;
        ull a00 = 0, a01 = 0, a10 = 0, a11 = 0;
        #pragma unroll 8
        for (int c4 = 0; c4 < DIM; c4 += 4) {
            ulonglong2 kb0 = *(const ulonglong2*)&sm.Kb[i0][c4];
            ulonglong2 kb1 = *(const ulonglong2*)&sm.Kb[i0 + 1][c4];
            ulonglong2 qn0 = *(const ulonglong2*)&sm.Qn[i0][c4];
            ulonglong2 qn1 = *(const ulonglong2*)&sm.Qn[i0 + 1][c4];
            ulonglong2 kn0 = *(const ulonglong2*)&sm.Kn[j0][c4];
            ulonglong2 kn1 = *(const ulonglong2*)&sm.Kn[j0 + 1][c4];
            t00 = ffma2(kb0.x, kn0.x, t00); t00 = ffma2(kb0.y, kn0.y, t00);
            t01 = ffma2(kb0.x, kn1.x, t01); t01 = ffma2(kb0.y, kn1.y, t01);
            t10 = ffma2(kb1.x, kn0.x, t10); t10 = ffma2(kb1.y, kn0.y, t10);
            t11 = ffma2(kb1.x, kn1.x, t11); t11 = ffma2(kb1.y, kn1.y, t11);
            a00 = ffma2(qn0.x, kn0.x, a00); a00 = ffma2(qn0.y, kn0.y, a00);
            a01 = ffma2(qn0.x, kn1.x, a01); a01 = ffma2(qn0.y, kn1.y, a01);
            a10 = ffma2(qn1.x, kn0.x, a10); a10 = ffma2(qn1.y, kn0.y, a10);
            a11 = ffma2(qn1.x, kn1.x, a11); a11 = ffma2(qn1.y, kn1.y, a11);
        }
        sm.T[i0][j0]         = (i0 > j0)         ? hadd2(t00) : 0.f;
        sm.T[i0][j0 + 1]     = (i0 > j0 + 1)     ? hadd2(t01) : 0.f;
        sm.T[i0 + 1][j0]     = (i0 + 1 > j0)     ? hadd2(t10) : 0.f;
        sm.T[i0 + 1][j0 + 1] = (i0 + 1 > j0 + 1) ? hadd2(t11) : 0.f;
        float* atg = g_AT + (size_t)(bh * NCHUNK + ch) * CHK * CHK;
        atg[i0 * CHK + j0]           = (i0 >= j0)         ? hadd2(a00) : 0.f;
        atg[i0 * CHK + j0 + 1]       = (i0 >= j0 + 1)     ? hadd2(a01) : 0.f;
        atg[(i0 + 1) * CHK + j0]     = (i0 + 1 >= j0)     ? hadd2(a10) : 0.f;
        atg[(i0 + 1) * CHK + j0 + 1] = (i0 + 1 >= j0 + 1) ? hadd2(a11) : 0.f;
    }
    __syncthreads();

    { // forward substitution: 256 threads = 256 rhs columns [kb | vb]
        const bool left = tid < DIM;
        const int col = left ? tid : tid - DIM;
        float x[CHK];
        #pragma unroll
        for (int i = 0; i < CHK; i++) x[i] = left ? sm.Kb[i][col] : sm.Vb[i][col];
        #pragma unroll
        for (int i = 1; i < CHK; i++) {
            float acc = x[i];
            #pragma unroll
            for (int m = 0; m < i; m++) acc -= sm.T[i][m] * x[m];
            x[i] = acc;
        }
        float* dst = (left ? g_W : g_U) + base + col;
        #pragma unroll
        for (int i = 0; i < CHK; i++) dst[(size_t)i * DIM] = x[i];
    }
}

// ============================================================
// Kernel 2: sequential scan, register-tiled, 512 threads
// ============================================================
struct Buf {
    float Qn [CHK][PD];
    float Kn [CHK][PD];
    float Wv [CHK][PD];
    float Ub [CHK][DV];
    float Atb[CHK][CHK];
};
struct SM2 {
    float St  [DV][PD];      // S^T slice: [j][c]
    float UAT [DV][36];      // (u - w@S)^T: [j][i]
    float Obuf[CHK][17];     // q@S partial, padded stride 17
    Buf   buf[2];
};

__device__ __forceinline__ void load_buf(Buf& B, int bh, int ch, int sl, int tid)
{
    const size_t base = ((size_t)bh * LSEQ + (size_t)ch * CHK) * DIM;
    const float* qs  = g_QN + base;
    const float* ks  = g_KN + base;
    const float* ws  = g_W  + base;
    const float* us  = g_U  + base + sl * DV;
    const float* ats = g_AT + (size_t)(bh * NCHUNK + ch) * CHK * CHK;

    #pragma unroll
    for (int t = tid; t < 1024; t += THR2) {
        int r = t >> 5, c4 = (t & 31) * 4;
        cp16(&B.Qn[r][c4], qs + r * DIM + c4);
        cp16(&B.Kn[r][c4], ks + r * DIM + c4);
        cp16(&B.Wv[r][c4], ws + r * DIM + c4);
    }
    if (tid < 128) {
        int r = tid >> 2, c4 = (tid & 3) * 4;
        cp16(&B.Ub[r][c4], us + r * DIM + c4);
    }
    if (tid < 256) {
        int r = tid >> 3, c4 = (tid & 7) * 4;
        cp16(&B.Atb[r][c4], ats + r * CHK + c4);
    }
}

extern "C" __global__ void __launch_bounds__(THR2, 1)
k2_scan(float* __restrict__ out, float* __restrict__ sfinal, int write_s)
{
    extern __shared__ __align__(16) char smraw2[];
    SM2& sm = *reinterpret_cast<SM2*>(smraw2);
    const int bh = blockIdx.x, sl = blockIdx.y;
    const int tid = threadIdx.x;

    float* ob = out + (size_t)bh * LSEQ * DIM + sl * DV;

    for (int idx = tid; idx < DV * DIM; idx += THR2)
        sm.St[idx >> 7][idx & 127] = 0.f;

    load_buf(sm.buf[0], bh, 0, sl, tid);
    cp_commit();

    // phase A decomposition: 2i x 4j tiles, 8-way c-split
    const int csplit = tid & 7;
    const int tileA  = tid >> 3;          // 0..63
    const int ia0 = (tileA & 15) * 2;
    const int ja0 = (tileA >> 4) * 4;
    const int ca0 = csplit * 16;

    // phase C1 decomposition: one (i,j) per thread
    const int i1 = tid >> 4, j1 = tid & 15;

    // phase C2 decomposition: 4js x 4c tiles, 4-way r-split
    const int rsp   = tid & 3;
    const int tileC = tid >> 2;           // 0..127
    const int jc0 = tileC & 3;            // js rows: jc0, jc0+4, jc0+8, jc0+12
    const int cc0 = (tileC >> 2) * 4;     // 0..124

    for (int ch = 0; ch < NCHUNK; ch++) {
        cp_wait_all();
        __syncthreads();
        if (ch + 1 < NCHUNK) {
            load_buf(sm.buf[(ch + 1) & 1], bh, ch + 1, sl, tid);
            cp_commit();
        }
        const Buf& B = sm.buf[ch & 1];

        // ---- phase A: O = qn@S, A = w@S over c in [ca0, ca0+16) ----
        {
            ull O2[2][4] = {}, A2[2][4] = {};
            #pragma unroll
            for (int cc = 0; cc < 16; cc += 4) {
                const int c4 = ca0 + cc;
                ulonglong2 q0 = *(const ulonglong2*)&B.Qn[ia0][c4];
                ulonglong2 q1 = *(const ulonglong2*)&B.Qn[ia0 + 1][c4];
                ulonglong2 w0 = *(const ulonglong2*)&B.Wv[ia0][c4];
                ulonglong2 w1 = *(const ulonglong2*)&B.Wv[ia0 + 1][c4];
                #pragma unroll
                for (int jj = 0; jj < 4; jj++) {
                    ulonglong2 s = *(const ulonglong2*)&sm.St[ja0 + jj][c4];
                    O2[0][jj] = ffma2(q0.x, s.x, O2[0][jj]);
                    O2[0][jj] = ffma2(q0.y, s.y, O2[0][jj]);
                    O2[1][jj] = ffma2(q1.x, s.x, O2[1][jj]);
                    O2[1][jj] = ffma2(q1.y, s.y, O2[1][jj]);
                    A2[0][jj] = ffma2(w0.x, s.x, A2[0][jj]);
                    A2[0][jj] = ffma2(w0.y, s.y, A2[0][jj]);
                    A2[1][jj] = ffma2(w1.x, s.x, A2[1][jj]);
                    A2[1][jj] = ffma2(w1.y, s.y, A2[1][jj]);
                }
            }
            float Ov[2][4], Av[2][4];
            #pragma unroll
            for (int ii = 0; ii < 2; ii++)
                #pragma unroll
                for (int jj = 0; jj < 4; jj++) {
                    Ov[ii][jj] = hadd2(O2[ii][jj]);
                    Av[ii][jj] = hadd2(A2[ii][jj]);
                }
            #pragma unroll
            for (int m = 4; m >= 1; m >>= 1) {
                #pragma unroll
                for (int ii = 0; ii < 2; ii++)
                    #pragma unroll
                    for (int jj = 0; jj < 4; jj++) {
                        Ov[ii][jj] += __shfl_xor_sync(0xffffffffu, Ov[ii][jj], m);
                        Av[ii][jj] += __shfl_xor_sync(0xffffffffu, Av[ii][jj], m);
                    }
            }
            if (csplit == 0) {
                #pragma unroll
                for (int ii = 0; ii < 2; ii++)
                    #pragma unroll
                    for (int jj = 0; jj < 4; jj++) {
                        sm.UAT[ja0 + jj][ia0 + ii] =
                            B.Ub[ia0 + ii][ja0 + jj] - Av[ii][jj];
                        sm.Obuf[ia0 + ii][ja0 + jj] = Ov[ii][jj];
                    }
            }
        }
        __syncthreads();

        // ---- phase C1: out = Obuf + At @ UA ----
        {
            ull o2 = 0;
            #pragma unroll
            for (int f4 = 0; f4 < CHK; f4 += 4) {
                ulonglong2 a2v = *(const ulonglong2*)&B.Atb[i1][f4];
                ulonglong2 u2v = *(const ulonglong2*)&sm.UAT[j1][f4];
                o2 = ffma2(a2v.x, u2v.x, o2);
                o2 = ffma2(a2v.y, u2v.y, o2);
            }
            ob[(size_t)(ch * CHK + i1) * DIM + j1] = sm.Obuf[i1][j1] + hadd2(o2);
        }

        // ---- phase C2: St[js][cc0..cc0+3] += sum_r UA[r][js]*kn[r][c] ----
        {
            ull acc[4][2] = {};
            #pragma unroll
            for (int it = 0; it < 8; it++) {
                const int r = it * 4 + rsp;
                ulonglong2 kv = *(const ulonglong2*)&B.Kn[r][cc0];
                #pragma unroll
                for (int jj = 0; jj < 4; jj++) {
                    ull u = pack2(sm.UAT[jc0 + 4 * jj][r]);
                    acc[jj][0] = ffma2(u, kv.x, acc[jj][0]);
                    acc[jj][1] = ffma2(u, kv.y, acc[jj][1]);
                }
            }
            #pragma unroll
            for (int m = 2; m >= 1; m >>= 1) {
                #pragma unroll
                for (int jj = 0; jj < 4; jj++) {
                    acc[jj][0] = fadd2(acc[jj][0], shfl_xor64(acc[jj][0], m));
                    acc[jj][1] = fadd2(acc[jj][1], shfl_xor64(acc[jj][1], m));
                }
            }
            if (rsp == 0) {
                #pragma unroll
                for (int jj = 0; jj < 4; jj++) {
                    ulonglong2* p = (ulonglong2*)&sm.St[jc0 + 4 * jj][cc0];
                    ulonglong2 v = *p;
                    v.x = fadd2(v.x, acc[jj][0]);
                    v.y = fadd2(v.y, acc[jj][1]);
                    *p = v;
                }
            }
        }
        // loop-top barrier separates C2's St writes from next phase-A reads
    }

    if (write_s) {
        __syncthreads();
        float* sf = sfinal + (size_t)bh * DIM * DIM + sl * DV;
        for (int idx = tid; idx < DIM * DV; idx += THR2) {
            int c = idx >> 4, jv = idx & 15;
            sf[(size_t)c * DIM + jv] = sm.St[jv][c];
        }
    }
}

// ============================================================
extern "C" void kernel_launch(void* const* d_in, const int* in_sizes, int n_in,
                              void* d_out, int out_size) {
    const float* q    = (const float*)d_in[0];
    const float* k    = (const float*)d_in[1];
    const float* v    = (const float*)d_in[2];
    const float* beta = (const float*)d_in[3];
    float* out = (float*)d_out;

    const int out_elems = BH * LSEQ * DIM;
    const int s_elems   = BH * DIM * DIM;
    int write_s = (out_size >= out_elems + s_elems) ? 1 : 0;
    float* sf = out + out_elems;

    static bool attr_done = false;
    if (!attr_done) {
        cudaFuncSetAttribute(k1_prepare, cudaFuncAttributeMaxDynamicSharedMemorySize,
                             (int)sizeof(SM1));
        cudaFuncSetAttribute(k2_scan, cudaFuncAttributeMaxDynamicSharedMemorySize,
                             (int)sizeof(SM2));
        attr_done = true;
    }

    dim3 g1(NCHUNK, BH);
    k1_prepare<<<g1, 256, sizeof(SM1)>>>(q, k, v, beta);

    dim3 g2(BH, NSLICE);
    k2_scan<<<g2, THR2, sizeof(SM2)>>>(out, sf, write_s);
}

// round 7
// speedup vs baseline: 1.6229x; 1.6229x over previous
#include <cuda_runtime.h>
#include <cstdint>

#define BH      16
#define LSEQ    4096
#define DIM     128
#define CHK     32
#define DV      16
#define NSLICE  8
#define NCHUNK  (LSEQ / CHK)
#define PD      132   // padded row length (floats), 528B, 16B-aligned
#define ATP     36    // Atb/UAT padded stride (144B, 16B-aligned, conflict-free)
#define THR2    512

typedef unsigned long long ull;

// ---- scratch (device globals; allocation-free) ----
__device__ float g_QN[(size_t)BH * LSEQ * DIM];
__device__ float g_KN[(size_t)BH * LSEQ * DIM];
__device__ float g_W [(size_t)BH * LSEQ * DIM];
__device__ float g_U [(size_t)BH * LSEQ * DIM];
__device__ float g_AT[(size_t)BH * NCHUNK * CHK * CHK];

// ---- packed f32x2 helpers ----
__device__ __forceinline__ ull ffma2(ull a, ull b, ull c) {
    ull d;
    asm("fma.rn.f32x2 %0, %1, %2, %3;" : "=l"(d) : "l"(a), "l"(b), "l"(c));
    return d;
}
__device__ __forceinline__ ull fadd2(ull a, ull b) {
    ull d;
    asm("add.rn.f32x2 %0, %1, %2;" : "=l"(d) : "l"(a), "l"(b));
    return d;
}
__device__ __forceinline__ ull pack2(float v) {
    ull d;
    asm("mov.b64 %0, {%1, %1};" : "=l"(d) : "f"(v));
    return d;
}
__device__ __forceinline__ float hadd2(ull v) {
    float lo, hi;
    asm("mov.b64 {%0, %1}, %2;" : "=f"(lo), "=f"(hi) : "l"(v));
    return lo + hi;
}

// ---- cp.async helpers ----
__device__ __forceinline__ void cp16(void* smem_dst, const void* gmem_src) {
    uint32_t s = (uint32_t)__cvta_generic_to_shared(smem_dst);
    asm volatile("cp.async.cg.shared.global [%0], [%1], 16;\n" :: "r"(s), "l"(gmem_src));
}
__device__ __forceinline__ void cp_commit() {
    asm volatile("cp.async.commit_group;\n" ::: "memory");
}
__device__ __forceinline__ void cp_wait_all() {
    asm volatile("cp.async.wait_group 0;\n" ::: "memory");
}

// ============================================================
// Kernel 1: fully parallel per-(bh,chunk) preparation
// ============================================================
struct SM1 {
    float Qn[CHK][PD];
    float Kn[CHK][PD];
    float Kb[CHK][PD];
    float Vb[CHK][PD];
    float T [CHK][CHK + 1];
    float beta[CHK], rq[CHK], rk[CHK];
};

extern "C" __global__ void __launch_bounds__(256)
k1_prepare(const float* __restrict__ q, const float* __restrict__ k,
           const float* __restrict__ v, const float* __restrict__ beta)
{
    extern __shared__ __align__(16) char smraw1[];
    SM1& sm = *reinterpret_cast<SM1*>(smraw1);
    const int ch = blockIdx.x, bh = blockIdx.y;
    const int tid = threadIdx.x, lane = tid & 31, warp = tid >> 5;
    const size_t base = ((size_t)bh * LSEQ + (size_t)ch * CHK) * DIM;

    for (int idx = tid; idx < CHK * DIM; idx += 256) {
        int r = idx >> 7, c = idx & 127;
        sm.Qn[r][c] = q[base + idx];
        sm.Kn[r][c] = k[base + idx];
        sm.Vb[r][c] = v[base + idx];
    }
    if (tid < CHK) sm.beta[tid] = beta[(size_t)bh * LSEQ + ch * CHK + tid];
    __syncthreads();

    { // row L2 norms
        int row = warp * 4 + (lane >> 3), sub = lane & 7;
        float sq = 0.f, sk = 0.f;
        #pragma unroll
        for (int t = 0; t < 16; t++) {
            float a  = sm.Qn[row][sub + 8 * t]; sq += a * a;
            float b2 = sm.Kn[row][sub + 8 * t]; sk += b2 * b2;
        }
        #pragma unroll
        for (int off = 4; off >= 1; off >>= 1) {
            sq += __shfl_xor_sync(0xffffffffu, sq, off);
            sk += __shfl_xor_sync(0xffffffffu, sk, off);
        }
        if (sub == 0) { sm.rq[row] = rsqrtf(sq); sm.rk[row] = rsqrtf(sk); }
    }
    __syncthreads();

    for (int idx = tid; idx < CHK * DIM; idx += 256) {
        int r = idx >> 7, c = idx & 127;
        float bt = sm.beta[r];
        float qn = sm.Qn[r][c] * sm.rq[r];
        float kn = sm.Kn[r][c] * sm.rk[r];
        sm.Qn[r][c] = qn;
        sm.Kn[r][c] = kn;
        sm.Kb[r][c] = kn * bt;
        sm.Vb[r][c] *= bt;
        g_QN[base + idx] = qn;
        g_KN[base + idx] = kn;
    }
    __syncthreads();

    { // T (strict lower, kb.kn) and At (causal, qn.kn), 2x2 tiles, f32x2 math
        int a = tid >> 4, b = tid & 15;
        int i0 = 2 * a, j0 = 2 * b;
        ull t00 = 0, t01 = 0, t10 = 0, t11 = 0;
        ull a00 = 0, a01 = 0, a10 = 0, a11 = 0;
        #pragma unroll 8
        for (int c4 = 0; c4 < DIM; c4 += 4) {
            ulonglong2 kb0 = *(const ulonglong2*)&sm.Kb[i0][c4];
            ulonglong2 kb1 = *(const ulonglong2*)&sm.Kb[i0 + 1][c4];
            ulonglong2 qn0 = *(const ulonglong2*)&sm.Qn[i0][c4];
            ulonglong2 qn1 = *(const ulonglong2*)&sm.Qn[i0 + 1][c4];
            ulonglong2 kn0 = *(const ulonglong2*)&sm.Kn[j0][c4];
            ulonglong2 kn1 = *(const ulonglong2*)&sm.Kn[j0 + 1][c4];
            t00 = ffma2(kb0.x, kn0.x, t00); t00 = ffma2(kb0.y, kn0.y, t00);
            t01 = ffma2(kb0.x, kn1.x, t01); t01 = ffma2(kb0.y, kn1.y, t01);
            t10 = ffma2(kb1.x, kn0.x, t10); t10 = ffma2(kb1.y, kn0.y, t10);
            t11 = ffma2(kb1.x, kn1.x, t11); t11 = ffma2(kb1.y, kn1.y, t11);
            a00 = ffma2(qn0.x, kn0.x, a00); a00 = ffma2(qn0.y, kn0.y, a00);
            a01 = ffma2(qn0.x, kn1.x, a01); a01 = ffma2(qn0.y, kn1.y, a01);
            a10 = ffma2(qn1.x, kn0.x, a10); a10 = ffma2(qn1.y, kn0.y, a10);
            a11 = ffma2(qn1.x, kn1.x, a11); a11 = ffma2(qn1.y, kn1.y, a11);
        }
        sm.T[i0][j0]         = (i0 > j0)         ? hadd2(t00) : 0.f;
        sm.T[i0][j0 + 1]     = (i0 > j0 + 1)     ? hadd2(t01) : 0.f;
        sm.T[i0 + 1][j0]     = (i0 + 1 > j0)     ? hadd2(t10) : 0.f;
        sm.T[i0 + 1][j0 + 1] = (i0 + 1 > j0 + 1) ? hadd2(t11) : 0.f;
        float* atg = g_AT + (size_t)(bh * NCHUNK + ch) * CHK * CHK;
        atg[i0 * CHK + j0]           = (i0 >= j0)         ? hadd2(a00) : 0.f;
        atg[i0 * CHK + j0 + 1]       = (i0 >= j0 + 1)     ? hadd2(a01) : 0.f;
        atg[(i0 + 1) * CHK + j0]     = (i0 + 1 >= j0)     ? hadd2(a10) : 0.f;
        atg[(i0 + 1) * CHK + j0 + 1] = (i0 + 1 >= j0 + 1) ? hadd2(a11) : 0.f;
    }
    __syncthreads();

    { // forward substitution: 256 threads = 256 rhs columns [kb | vb]
        const bool left = tid < DIM;
        const int col = left ? tid : tid - DIM;
        float x[CHK];
        #pragma unroll
        for (int i = 0; i < CHK; i++) x[i] = left ? sm.Kb[i][col] : sm.Vb[i][col];
        #pragma unroll
        for (int i = 1; i < CHK; i++) {
            float acc = x[i];
            #pragma unroll
            for (int m = 0; m < i; m++) acc -= sm.T[i][m] * x[m];
            x[i] = acc;
        }
        float* dst = (left ? g_W : g_U) + base + col;
        #pragma unroll
        for (int i = 0; i < CHK; i++) dst[(size_t)i * DIM] = x[i];
    }
}

// ============================================================
// Kernel 2: sequential scan, bank-exact tiling, 512 threads
// ============================================================
struct Buf {
    float Qn [CHK][PD];
    float Kn [CHK][PD];
    float Wv [CHK][PD];
    float Ub [CHK][DV];
    float Atb[CHK][ATP];   // padded: row stride 144B -> conflict-free
};
struct SM2 {
    float St [DV][PD];     // S^T slice: [j][c]
    float UAT[DV][ATP];    // (u - w@S)^T: [j][i]
    Buf   buf[2];
};

__device__ __forceinline__ void load_buf(Buf& B, int bh, int ch, int sl, int tid)
{
    const size_t base = ((size_t)bh * LSEQ + (size_t)ch * CHK) * DIM;
    const float* qs  = g_QN + base;
    const float* ks  = g_KN + base;
    const float* ws  = g_W  + base;
    const float* us  = g_U  + base + sl * DV;
    const float* ats = g_AT + (size_t)(bh * NCHUNK + ch) * CHK * CHK;

    #pragma unroll
    for (int t = tid; t < 1024; t += THR2) {
        int r = t >> 5, c4 = (t & 31) * 4;
        cp16(&B.Qn[r][c4], qs + r * DIM + c4);
        cp16(&B.Kn[r][c4], ks + r * DIM + c4);
        cp16(&B.Wv[r][c4], ws + r * DIM + c4);
    }
    if (tid < 128) {
        int r = tid >> 2, c4 = (tid & 3) * 4;
        cp16(&B.Ub[r][c4], us + r * DIM + c4);
    }
    if (tid < 256) {
        int r = tid >> 3, c4 = (tid & 7) * 4;
        cp16(&B.Atb[r][c4], ats + r * CHK + c4);
    }
}

extern "C" __global__ void __launch_bounds__(THR2, 1)
k2_scan(float* __restrict__ out, float* __restrict__ sfinal, int write_s)
{
    extern __shared__ __align__(16) char smraw2[];
    SM2& sm = *reinterpret_cast<SM2*>(smraw2);
    const int bh = blockIdx.x, sl = blockIdx.y;
    const int tid = threadIdx.x;
    const int warp = tid >> 5, lane = tid & 31;

    float* ob = out + (size_t)bh * LSEQ * DIM + sl * DV;

    for (int idx = tid; idx < DV * DIM; idx += THR2)
        sm.St[idx >> 7][idx & 127] = 0.f;

    load_buf(sm.buf[0], bh, 0, sl, tid);
    cp_commit();

    // phase A / C1 ownership: warp grid 8(wi) x 2(wj); lane grid 4(i) x 8(j)
    const int ai = (warp >> 1) * 4 + (lane >> 3);   // 0..31
    const int aj = (warp & 1)  * 8 + (lane & 7);    // 0..15

    // phase C2 ownership (warps 0..3): warp w -> js rows {w, w+4, w+8, w+12}
    const int c0 = lane * 4;                        // 0..124

    for (int ch = 0; ch < NCHUNK; ch++) {
        cp_wait_all();
        __syncthreads();
        if (ch + 1 < NCHUNK) {
            load_buf(sm.buf[(ch + 1) & 1], bh, ch + 1, sl, tid);
            cp_commit();
        }
        const Buf& B = sm.buf[ch & 1];

        // ---- phase A: O = qn@S, A = w@S (full c per thread; all loads cf) ----
        ull O2 = 0, A2 = 0;
        #pragma unroll 16
        for (int c4 = 0; c4 < DIM; c4 += 4) {
            ulonglong2 q2 = *(const ulonglong2*)&B.Qn[ai][c4];
            ulonglong2 w2 = *(const ulonglong2*)&B.Wv[ai][c4];
            ulonglong2 s2 = *(const ulonglong2*)&sm.St[aj][c4];
            O2 = ffma2(q2.x, s2.x, O2); O2 = ffma2(q2.y, s2.y, O2);
            A2 = ffma2(w2.x, s2.x, A2); A2 = ffma2(w2.y, s2.y, A2);
        }
        float Ov = hadd2(O2);
        sm.UAT[aj][ai] = B.Ub[ai][aj] - hadd2(A2);
        __syncthreads();

        // ---- phase C1: out = O + At @ UA  (O still in register) ----
        {
            ull o2 = 0;
            #pragma unroll
            for (int f4 = 0; f4 < CHK; f4 += 4) {
                ulonglong2 a2v = *(const ulonglong2*)&B.Atb[ai][f4];
                ulonglong2 u2v = *(const ulonglong2*)&sm.UAT[aj][f4];
                o2 = ffma2(a2v.x, u2v.x, o2);
                o2 = ffma2(a2v.y, u2v.y, o2);
            }
            ob[(size_t)(ch * CHK + ai) * DIM + aj] = Ov + hadd2(o2);
        }

        // ---- phase C2 (warps 0..3): St[js][c0..3] += sum_r UA[r][js]*kn[r][c] ----
        if (tid < 128) {
            ull acc[4][2] = {};
            #pragma unroll
            for (int r0 = 0; r0 < CHK; r0 += 4) {
                float4 u0 = *(const float4*)&sm.UAT[warp     ][r0];
                float4 u1 = *(const float4*)&sm.UAT[warp + 4 ][r0];
                float4 u2 = *(const float4*)&sm.UAT[warp + 8 ][r0];
                float4 u3 = *(const float4*)&sm.UAT[warp + 12][r0];
                #pragma unroll
                for (int rr = 0; rr < 4; rr++) {
                    ulonglong2 kv = *(const ulonglong2*)&B.Kn[r0 + rr][c0];
                    float s0 = (rr == 0) ? u0.x : (rr == 1) ? u0.y : (rr == 2) ? u0.z : u0.w;
                    float s1 = (rr == 0) ? u1.x : (rr == 1) ? u1.y : (rr == 2) ? u1.z : u1.w;
                    float s2 = (rr == 0) ? u2.x : (rr == 1) ? u2.y : (rr == 2) ? u2.z : u2.w;
                    float s3 = (rr == 0) ? u3.x : (rr == 1) ? u3.y : (rr == 2) ? u3.z : u3.w;
                    ull p0 = pack2(s0), p1 = pack2(s1), p2 = pack2(s2), p3 = pack2(s3);
                    acc[0][0] = ffma2(p0, kv.x, acc[0][0]); acc[0][1] = ffma2(p0, kv.y, acc[0][1]);
                    acc[1][0] = ffma2(p1, kv.x, acc[1][0]); acc[1][1] = ffma2(p1, kv.y, acc[1][1]);
                    acc[2][0] = ffma2(p2, kv.x, acc[2][0]); acc[2][1] = ffma2(p2, kv.y, acc[2][1]);
                    acc[3][0] = ffma2(p3, kv.x, acc[3][0]); acc[3][1] = ffma2(p3, kv.y, acc[3][1]);
                }
            }
            #pragma unroll
            for (int jj = 0; jj < 4; jj++) {
                ulonglong2* p = (ulonglong2*)&sm.St[warp + 4 * jj][c0];
                ulonglong2 v = *p;
                v.x = fadd2(v.x, acc[jj][0]);
                v.y = fadd2(v.y, acc[jj][1]);
                *p = v;
            }
        }
        // loop-top barrier separates C2's St writes from next phase-A reads
    }

    if (write_s) {
        __syncthreads();
        float* sf = sfinal + (size_t)bh * DIM * DIM + sl * DV;
        for (int idx = tid; idx < DIM * DV; idx += THR2) {
            int c = idx >> 4, jv = idx & 15;
            sf[(size_t)c * DIM + jv] = sm.St[jv][c];
        }
    }
}

// ============================================================
extern "C" void kernel_launch(void* const* d_in, const int* in_sizes, int n_in,
                              void* d_out, int out_size) {
    const float* q    = (const float*)d_in[0];
    const float* k    = (const float*)d_in[1];
    const float* v    = (const float*)d_in[2];
    const float* beta = (const float*)d_in[3];
    float* out = (float*)d_out;

    const int out_elems = BH * LSEQ * DIM;
    const int s_elems   = BH * DIM * DIM;
    int write_s = (out_size >= out_elems + s_elems) ? 1 : 0;
    float* sf = out + out_elems;

    static bool attr_done = false;
    if (!attr_done) {
        cudaFuncSetAttribute(k1_prepare, cudaFuncAttributeMaxDynamicSharedMemorySize,
                             (int)sizeof(SM1));
        cudaFuncSetAttribute(k2_scan, cudaFuncAttributeMaxDynamicSharedMemorySize,
                             (int)sizeof(SM2));
        attr_done = true;
    }

    dim3 g1(NCHUNK, BH);
    k1_prepare<<<g1, 256, sizeof(SM1)>>>(q, k, v, beta);

    dim3 g2(BH, NSLICE);
    k2_scan<<<g2, THR2, sizeof(SM2)>>>(out, sf, write_s);
}

// round 8
// speedup vs baseline: 1.8475x; 1.1383x over previous
#include <cuda_runtime.h>
#include <cstdint>

#define BH      16
#define LSEQ    4096
#define DIM     128
#define CHK     32
#define DV      16
#define NSLICE  8
#define NCHUNK  (LSEQ / CHK)
#define PD      132   // padded row length (floats), 528B, 16B-aligned
#define ATP     36    // Atb/UAT padded stride (144B, 16B-aligned, conflict-free)
#define THR2    512

typedef unsigned long long ull;

// ---- scratch (device globals; allocation-free) ----
__device__ float g_QN[(size_t)BH * LSEQ * DIM];
__device__ float g_KN[(size_t)BH * LSEQ * DIM];
__device__ float g_W [(size_t)BH * LSEQ * DIM];
__device__ float g_U [(size_t)BH * LSEQ * DIM];
__device__ float g_AT[(size_t)BH * NCHUNK * CHK * CHK];

// ---- packed f32x2 helpers ----
__device__ __forceinline__ ull ffma2(ull a, ull b, ull c) {
    ull d;
    asm("fma.rn.f32x2 %0, %1, %2, %3;" : "=l"(d) : "l"(a), "l"(b), "l"(c));
    return d;
}
__device__ __forceinline__ ull fadd2(ull a, ull b) {
    ull d;
    asm("add.rn.f32x2 %0, %1, %2;" : "=l"(d) : "l"(a), "l"(b));
    return d;
}
__device__ __forceinline__ ull pack2(float v) {
    ull d;
    asm("mov.b64 %0, {%1, %1};" : "=l"(d) : "f"(v));
    return d;
}
__device__ __forceinline__ float hadd2(ull v) {
    float lo, hi;
    asm("mov.b64 {%0, %1}, %2;" : "=f"(lo), "=f"(hi) : "l"(v));
    return lo + hi;
}

// ---- cp.async helpers ----
__device__ __forceinline__ void cp16(void* smem_dst, const void* gmem_src) {
    uint32_t s = (uint32_t)__cvta_generic_to_shared(smem_dst);
    asm volatile("cp.async.cg.shared.global [%0], [%1], 16;\n" :: "r"(s), "l"(gmem_src));
}
__device__ __forceinline__ void cp_commit() {
    asm volatile("cp.async.commit_group;\n" ::: "memory");
}
__device__ __forceinline__ void cp_wait_all() {
    asm volatile("cp.async.wait_group 0;\n" ::: "memory");
}

// ============================================================
// Kernel 1: fully parallel per-(bh,chunk) preparation
// ============================================================
struct SM1 {
    float Qn[CHK][PD];
    float Kn[CHK][PD];
    float Kb[CHK][PD];
    float Vb[CHK][PD];
    float T [CHK][CHK + 1];
    float beta[CHK], rq[CHK], rk[CHK];
};

extern "C" __global__ void __launch_bounds__(256)
k1_prepare(const float* __restrict__ q, const float* __restrict__ k,
           const float* __restrict__ v, const float* __restrict__ beta)
{
    extern __shared__ __align__(16) char smraw1[];
    SM1& sm = *reinterpret_cast<SM1*>(smraw1);
    const int ch = blockIdx.x, bh = blockIdx.y;
    const int tid = threadIdx.x, lane = tid & 31, warp = tid >> 5;
    const size_t base = ((size_t)bh * LSEQ + (size_t)ch * CHK) * DIM;

    for (int idx = tid; idx < CHK * DIM; idx += 256) {
        int r = idx >> 7, c = idx & 127;
        sm.Qn[r][c] = q[base + idx];
        sm.Kn[r][c] = k[base + idx];
        sm.Vb[r][c] = v[base + idx];
    }
    if (tid < CHK) sm.beta[tid] = beta[(size_t)bh * LSEQ + ch * CHK + tid];
    __syncthreads();

    { // row L2 norms
        int row = warp * 4 + (lane >> 3), sub = lane & 7;
        float sq = 0.f, sk = 0.f;
        #pragma unroll
        for (int t = 0; t < 16; t++) {
            float a  = sm.Qn[row][sub + 8 * t]; sq += a * a;
            float b2 = sm.Kn[row][sub + 8 * t]; sk += b2 * b2;
        }
        #pragma unroll
        for (int off = 4; off >= 1; off >>= 1) {
            sq += __shfl_xor_sync(0xffffffffu, sq, off);
            sk += __shfl_xor_sync(0xffffffffu, sk, off);
        }
        if (sub == 0) { sm.rq[row] = rsqrtf(sq); sm.rk[row] = rsqrtf(sk); }
    }
    __syncthreads();

    for (int idx = tid; idx < CHK * DIM; idx += 256) {
        int r = idx >> 7, c = idx & 127;
        float bt = sm.beta[r];
        float qn = sm.Qn[r][c] * sm.rq[r];
        float kn = sm.Kn[r][c] * sm.rk[r];
        sm.Qn[r][c] = qn;
        sm.Kn[r][c] = kn;
        sm.Kb[r][c] = kn * bt;
        sm.Vb[r][c] *= bt;
        g_QN[base + idx] = qn;
        g_KN[base + idx] = kn;
    }
    __syncthreads();

    { // T (strict lower, kb.kn) and At (causal, qn.kn), 2x2 tiles, f32x2 math
        int a = tid >> 4, b = tid & 15;
        int i0 = 2 * a, j0 = 2 * b;
        ull t00 = 0, t01 = 0, t10 = 0, t11 = 0;
        ull a00 = 0, a01 = 0, a10 = 0, a11 = 0;
        #pragma unroll 8
        for (int c4 = 0; c4 < DIM; c4 += 4) {
            ulonglong2 kb0 = *(const ulonglong2*)&sm.Kb[i0][c4];
            ulonglong2 kb1 = *(const ulonglong2*)&sm.Kb[i0 + 1][c4];
            ulonglong2 qn0 = *(const ulonglong2*)&sm.Qn[i0][c4];
            ulonglong2 qn1 = *(const ulonglong2*)&sm.Qn[i0 + 1][c4];
            ulonglong2 kn0 = *(const ulonglong2*)&sm.Kn[j0][c4];
            ulonglong2 kn1 = *(const ulonglong2*)&sm.Kn[j0 + 1][c4];
            t00 = ffma2(kb0.x, kn0.x, t00); t00 = ffma2(kb0.y, kn0.y, t00);
            t01 = ffma2(kb0.x, kn1.x, t01); t01 = ffma2(kb0.y, kn1.y, t01);
            t10 = ffma2(kb1.x, kn0.x, t10); t10 = ffma2(kb1.y, kn0.y, t10);
            t11 = ffma2(kb1.x, kn1.x, t11); t11 = ffma2(kb1.y, kn1.y, t11);
            a00 = ffma2(qn0.x, kn0.x, a00); a00 = ffma2(qn0.y, kn0.y, a00);
            a01 = ffma2(qn0.x, kn1.x, a01); a01 = ffma2(qn0.y, kn1.y, a01);
            a10 = ffma2(qn1.x, kn0.x, a10); a10 = ffma2(qn1.y, kn0.y, a10);
            a11 = ffma2(qn1.x, kn1.x, a11); a11 = ffma2(qn1.y, kn1.y, a11);
        }
        sm.T[i0][j0]         = (i0 > j0)         ? hadd2(t00) : 0.f;
        sm.T[i0][j0 + 1]     = (i0 > j0 + 1)     ? hadd2(t01) : 0.f;
        sm.T[i0 + 1][j0]     = (i0 + 1 > j0)     ? hadd2(t10) : 0.f;
        sm.T[i0 + 1][j0 + 1] = (i0 + 1 > j0 + 1) ? hadd2(t11) : 0.f;
        float* atg = g_AT + (size_t)(bh * NCHUNK + ch) * CHK * CHK;
        atg[i0 * CHK + j0]           = (i0 >= j0)         ? hadd2(a00) : 0.f;
        atg[i0 * CHK + j0 + 1]       = (i0 >= j0 + 1)     ? hadd2(a01) : 0.f;
        atg[(i0 + 1) * CHK + j0]     = (i0 + 1 >= j0)     ? hadd2(a10) : 0.f;
        atg[(i0 + 1) * CHK + j0 + 1] = (i0 + 1 >= j0 + 1) ? hadd2(a11) : 0.f;
    }
    __syncthreads();

    { // forward substitution: 256 threads = 256 rhs columns [kb | vb]
        const bool left = tid < DIM;
        const int col = left ? tid : tid - DIM;
        float x[CHK];
        #pragma unroll
        for (int i = 0; i < CHK; i++) x[i] = left ? sm.Kb[i][col] : sm.Vb[i][col];
        #pragma unroll
        for (int i = 1; i < CHK; i++) {
            float acc = x[i];
            #pragma unroll
            for (int m = 0; m < i; m++) acc -= sm.T[i][m] * x[m];
            x[i] = acc;
        }
        float* dst = (left ? g_W : g_U) + base + col;
        #pragma unroll
        for (int i = 0; i < CHK; i++) dst[(size_t)i * DIM] = x[i];
    }
}

// ============================================================
// Kernel 2: sequential scan; phase-A register tiles (bank-exact),
//           C1 (warps 4-15) overlapped with C2 (warps 0-3)
// ============================================================
struct Buf {
    float Qn [CHK][PD];
    float Kn [CHK][PD];
    float Wv [CHK][PD];
    float Ub [CHK][DV];
    float Atb[CHK][ATP];
};
struct SM2 {
    float St  [DV][PD];     // S^T slice: [j][c]
    float UAT [DV][ATP];    // (u - w@S)^T: [j][i]
    float Obuf[CHK][17];    // q@S partials
    Buf   buf[2];
};

__device__ __forceinline__ void load_buf(Buf& B, int bh, int ch, int sl, int tid)
{
    const size_t base = ((size_t)bh * LSEQ + (size_t)ch * CHK) * DIM;
    const float* qs  = g_QN + base;
    const float* ks  = g_KN + base;
    const float* ws  = g_W  + base;
    const float* us  = g_U  + base + sl * DV;
    const float* ats = g_AT + (size_t)(bh * NCHUNK + ch) * CHK * CHK;

    #pragma unroll
    for (int t = tid; t < 1024; t += THR2) {
        int r = t >> 5, c4 = (t & 31) * 4;
        cp16(&B.Qn[r][c4], qs + r * DIM + c4);
        cp16(&B.Kn[r][c4], ks + r * DIM + c4);
        cp16(&B.Wv[r][c4], ws + r * DIM + c4);
    }
    if (tid < 128) {
        int r = tid >> 2, c4 = (tid & 3) * 4;
        cp16(&B.Ub[r][c4], us + r * DIM + c4);
    }
    if (tid < 256) {
        int r = tid >> 3, c4 = (tid & 7) * 4;
        cp16(&B.Atb[r][c4], ats + r * CHK + c4);
    }
}

extern "C" __global__ void __launch_bounds__(THR2, 1)
k2_scan(float* __restrict__ out, float* __restrict__ sfinal, int write_s)
{
    extern __shared__ __align__(16) char smraw2[];
    SM2& sm = *reinterpret_cast<SM2*>(smraw2);
    const int bh = blockIdx.x, sl = blockIdx.y;
    const int tid = threadIdx.x;
    const int warp = tid >> 5, lane = tid & 31;

    float* ob = out + (size_t)bh * LSEQ * DIM + sl * DV;

    for (int idx = tid; idx < DV * DIM; idx += THR2)
        sm.St[idx >> 7][idx & 127] = 0.f;

    load_buf(sm.buf[0], bh, 0, sl, tid);
    cp_commit();

    // phase A: thread = (tile, csplit); lanes 0..7 of each 8-group share a tile
    const int csplit = lane & 7;                 // c-split index (fast over lanes)
    const int tile   = warp * 4 + (lane >> 3);   // 0..63
    const int ia0 = (tile & 15) * 2;             // 0,2,..,30
    const int ja0 = (tile >> 4) * 4;             // 0,4,8,12

    // C2 ownership (warps 0..3): warp w -> js rows {w, w+4, w+8, w+12}
    const int c0 = lane * 4;

    for (int ch = 0; ch < NCHUNK; ch++) {
        cp_wait_all();
        __syncthreads();
        if (ch + 1 < NCHUNK) {
            load_buf(sm.buf[(ch + 1) & 1], bh, ch + 1, sl, tid);
            cp_commit();
        }
        const Buf& B = sm.buf[ch & 1];

        // ---- phase A: O = qn@S, A = w@S; 2i x 4j tile, 8-way c-split ----
        {
            ull O2[2][4] = {}, A2[2][4] = {};
            #pragma unroll
            for (int cc = 0; cc < 4; cc++) {
                const int c4 = csplit * 4 + cc * 32;  // contiguous granules per lane-group
                ulonglong2 q0 = *(const ulonglong2*)&B.Qn[ia0][c4];
                ulonglong2 q1 = *(const ulonglong2*)&B.Qn[ia0 + 1][c4];
                ulonglong2 w0 = *(const ulonglong2*)&B.Wv[ia0][c4];
                ulonglong2 w1 = *(const ulonglong2*)&B.Wv[ia0 + 1][c4];
                #pragma unroll
                for (int jj = 0; jj < 4; jj++) {
                    ulonglong2 s = *(const ulonglong2*)&sm.St[ja0 + jj][c4];
                    O2[0][jj] = ffma2(q0.x, s.x, O2[0][jj]);
                    O2[0][jj] = ffma2(q0.y, s.y, O2[0][jj]);
                    O2[1][jj] = ffma2(q1.x, s.x, O2[1][jj]);
                    O2[1][jj] = ffma2(q1.y, s.y, O2[1][jj]);
                    A2[0][jj] = ffma2(w0.x, s.x, A2[0][jj]);
                    A2[0][jj] = ffma2(w0.y, s.y, A2[0][jj]);
                    A2[1][jj] = ffma2(w1.x, s.x, A2[1][jj]);
                    A2[1][jj] = ffma2(w1.y, s.y, A2[1][jj]);
                }
            }
            float Ov[2][4], Av[2][4];
            #pragma unroll
            for (int ii = 0; ii < 2; ii++)
                #pragma unroll
                for (int jj = 0; jj < 4; jj++) {
                    Ov[ii][jj] = hadd2(O2[ii][jj]);
                    Av[ii][jj] = hadd2(A2[ii][jj]);
                }
            #pragma unroll
            for (int m = 4; m >= 1; m >>= 1) {
                #pragma unroll
                for (int ii = 0; ii < 2; ii++)
                    #pragma unroll
                    for (int jj = 0; jj < 4; jj++) {
                        Ov[ii][jj] += __shfl_xor_sync(0xffffffffu, Ov[ii][jj], m);
                        Av[ii][jj] += __shfl_xor_sync(0xffffffffu, Av[ii][jj], m);
                    }
            }
            if (csplit == 0) {
                #pragma unroll
                for (int ii = 0; ii < 2; ii++)
                    #pragma unroll
                    for (int jj = 0; jj < 4; jj++) {
                        sm.UAT[ja0 + jj][ia0 + ii] =
                            B.Ub[ia0 + ii][ja0 + jj] - Av[ii][jj];
                        sm.Obuf[ia0 + ii][ja0 + jj] = Ov[ii][jj];
                    }
            }
        }
        __syncthreads();

        if (warp >= 4) {
            // ---- C1 (warps 4..15): out = Obuf + At @ UA, strided cells ----
            #pragma unroll 2
            for (int cell = tid - 128; cell < CHK * DV; cell += 384) {
                const int i1 = cell >> 4, j1 = cell & 15;
                ull o2 = 0;
                #pragma unroll
                for (int f4 = 0; f4 < CHK; f4 += 4) {
                    ulonglong2 a2v = *(const ulonglong2*)&B.Atb[i1][f4];
                    ulonglong2 u2v = *(const ulonglong2*)&sm.UAT[j1][f4];
                    o2 = ffma2(a2v.x, u2v.x, o2);
                    o2 = ffma2(a2v.y, u2v.y, o2);
                }
                ob[(size_t)(ch * CHK + i1) * DIM + j1] = sm.Obuf[i1][j1] + hadd2(o2);
            }
        } else {
            // ---- C2 (warps 0..3): St[js][c0..3] += sum_r UA[r][js]*kn[r][c] ----
            ull acc[4][2] = {};
            #pragma unroll
            for (int r0 = 0; r0 < CHK; r0 += 4) {
                float4 u0 = *(const float4*)&sm.UAT[warp     ][r0];
                float4 u1 = *(const float4*)&sm.UAT[warp + 4 ][r0];
                float4 u2 = *(const float4*)&sm.UAT[warp + 8 ][r0];
                float4 u3 = *(const float4*)&sm.UAT[warp + 12][r0];
                #pragma unroll
                for (int rr = 0; rr < 4; rr++) {
                    ulonglong2 kv = *(const ulonglong2*)&B.Kn[r0 + rr][c0];
                    float s0 = (rr == 0) ? u0.x : (rr == 1) ? u0.y : (rr == 2) ? u0.z : u0.w;
                    float s1 = (rr == 0) ? u1.x : (rr == 1) ? u1.y : (rr == 2) ? u1.z : u1.w;
                    float s2 = (rr == 0) ? u2.x : (rr == 1) ? u2.y : (rr == 2) ? u2.z : u2.w;
                    float s3 = (rr == 0) ? u3.x : (rr == 1) ? u3.y : (rr == 2) ? u3.z : u3.w;
                    ull p0 = pack2(s0), p1 = pack2(s1), p2 = pack2(s2), p3 = pack2(s3);
                    acc[0][0] = ffma2(p0, kv.x, acc[0][0]); acc[0][1] = ffma2(p0, kv.y, acc[0][1]);
                    acc[1][0] = ffma2(p1, kv.x, acc[1][0]); acc[1][1] = ffma2(p1, kv.y, acc[1][1]);
                    acc[2][0] = ffma2(p2, kv.x, acc[2][0]); acc[2][1] = ffma2(p2, kv.y, acc[2][1]);
                    acc[3][0] = ffma2(p3, kv.x, acc[3][0]); acc[3][1] = ffma2(p3, kv.y, acc[3][1]);
                }
            }
            #pragma unroll
            for (int jj = 0; jj < 4; jj++) {
                ulonglong2* p = (ulonglong2*)&sm.St[warp + 4 * jj][c0];
                ulonglong2 v = *p;
                v.x = fadd2(v.x, acc[jj][0]);
                v.y = fadd2(v.y, acc[jj][1]);
                *p = v;
            }
        }
        // loop-top barrier separates C2's St / A's UAT writes from next reads
    }

    if (write_s) {
        __syncthreads();
        float* sf = sfinal + (size_t)bh * DIM * DIM + sl * DV;
        for (int idx = tid; idx < DIM * DV; idx += THR2) {
            int c = idx >> 4, jv = idx & 15;
            sf[(size_t)c * DIM + jv] = sm.St[jv][c];
        }
    }
}

// ============================================================
extern "C" void kernel_launch(void* const* d_in, const int* in_sizes, int n_in,
                              void* d_out, int out_size) {
    const float* q    = (const float*)d_in[0];
    const float* k    = (const float*)d_in[1];
    const float* v    = (const float*)d_in[2];
    const float* beta = (const float*)d_in[3];
    float* out = (float*)d_out;

    const int out_elems = BH * LSEQ * DIM;
    const int s_elems   = BH * DIM * DIM;
    int write_s = (out_size >= out_elems + s_elems) ? 1 : 0;
    float* sf = out + out_elems;

    static bool attr_done = false;
    if (!attr_done) {
        cudaFuncSetAttribute(k1_prepare, cudaFuncAttributeMaxDynamicSharedMemorySize,
                             (int)sizeof(SM1));
        cudaFuncSetAttribute(k2_scan, cudaFuncAttributeMaxDynamicSharedMemorySize,
                             (int)sizeof(SM2));
        attr_done = true;
    }

    dim3 g1(NCHUNK, BH);
    k1_prepare<<<g1, 256, sizeof(SM1)>>>(q, k, v, beta);

    dim3 g2(BH, NSLICE);
    k2_scan<<<g2, THR2, sizeof(SM2)>>>(out, sf, write_s);
}